// round 2
// baseline (speedup 1.0000x reference)
#include <cuda_runtime.h>
#include <cuda_bf16.h>

// Persistent 2-layer LSTM, B=128, T=1024, H=512.
// 128 blocks x 256 threads, one block per SM. Each block owns 4 hidden
// columns of each layer (16 gate rows per layer). Recurrent weights are
// cached in shared memory, pre-packed as duplicated f32 pairs so the inner
// GEMM loops run on fma.rn.f32x2 (full-rate fp32 on sm_10x).
//
// Two grid barriers per timestep (h1-ready, h2-ready) via an epoch/counter
// software barrier. Per-thread __threadfence() before arrival provides both
// release ordering and the L1D invalidate (CCTL.IVALL) needed because h1/h2
// are broadcast through L2 between SMs.

typedef unsigned long long ull;

#define NBLK   128
#define NTHR   256
#define TSTEPS 1024
#define HDIM   512

// -------- packed f32x2 helpers --------
__device__ __forceinline__ ull ffma2(ull a, ull b, ull c) {
    ull d;
    asm("fma.rn.f32x2 %0, %1, %2, %3;" : "=l"(d) : "l"(a), "l"(b), "l"(c));
    return d;
}
__device__ __forceinline__ float f2lo(ull v) {
    return __uint_as_float((unsigned)(v & 0xffffffffULL));
}
__device__ __forceinline__ float f2hi(ull v) {
    return __uint_as_float((unsigned)(v >> 32));
}
__device__ __forceinline__ ull packf2(float a, float b) {
    return ((ull)__float_as_uint(b) << 32) | (ull)__float_as_uint(a);
}

__device__ __forceinline__ float sigf(float v) {
    return __fdividef(1.0f, 1.0f + __expf(-v));
}

// -------- global state (no allocations allowed) --------
__device__ ull g_h1a[HDIM * 64];   // h1 ping  [k][batch-pair]
__device__ ull g_h1b[HDIM * 64];   // h1 pong
__device__ ull g_h2 [HDIM * 64];   // h2       [k][batch-pair]
__device__ unsigned g_cnt;         // barrier counter (returns to 0 each barrier)
__device__ unsigned g_epoch;       // barrier epoch (monotonic across launches)

// -------- grid-wide barrier --------
__device__ __forceinline__ void gridbar() {
    __threadfence();                 // release + L1D invalidate (gpu scope)
    __syncthreads();
    if (threadIdx.x == 0) {
        unsigned e;
        asm volatile("ld.acquire.gpu.u32 %0, [%1];" : "=r"(e) : "l"(&g_epoch));
        unsigned r = atomicAdd(&g_cnt, 1u);
        if (r == NBLK - 1) {
            atomicExch(&g_cnt, 0u);
            __threadfence();
            atomicAdd(&g_epoch, 1u);
        } else {
            unsigned cur;
            do {
                asm volatile("ld.acquire.gpu.u32 %0, [%1];" : "=r"(cur) : "l"(&g_epoch));
            } while (cur == e);
        }
    }
    __syncthreads();
}

// -------- weight loader: 16 rows of W packed/duplicated into smem --------
__device__ void load_packed(ull* dst, const float* __restrict__ W, int blk, int tid) {
    for (int idx = tid; idx < 16 * HDIM; idx += NTHR) {
        int row = idx >> 9;          // 0..15  (= cg*4 + g)
        int k   = idx & 511;
        int cgl = row >> 2;
        int g   = row & 3;
        int r   = (blk << 2) + cgl + (g << 9);   // global gate row
        unsigned u = __float_as_uint(W[r * HDIM + k]);
        dst[idx] = ((ull)u << 32) | (ull)u;
    }
}

__global__ void __launch_bounds__(NTHR, 1)
lstm_persistent(const float* __restrict__ x,
                const float* __restrict__ Wih1, const float* __restrict__ Whh1,
                const float* __restrict__ bih1, const float* __restrict__ bhh1,
                const float* __restrict__ Wih2, const float* __restrict__ Whh2,
                const float* __restrict__ bih2, const float* __restrict__ bhh2,
                const float* __restrict__ Wlin, const float* __restrict__ blin,
                float* __restrict__ out)
{
    extern __shared__ ull sm[];
    ull*   sW1   = sm;                 // Whh1 packed  [16][512]
    ull*   sWh2  = sm + 8192;          // Whh2 packed
    ull*   sWi2  = sm + 16384;         // Wih2 packed
    float* sWlin = (float*)(sm + 24576);
    float* sRed  = sWlin + HDIM;

    const int tid = threadIdx.x;
    const int blk = blockIdx.x;
    const int bp  = tid & 63;          // batch pair (batches 2bp, 2bp+1)
    const int cg  = tid >> 6;          // column-in-block 0..3
    const int m   = (blk << 2) + cg;   // owned hidden column

    load_packed(sW1,  Whh1, blk, tid);
    load_packed(sWh2, Whh2, blk, tid);
    load_packed(sWi2, Wih2, blk, tid);
    for (int i = tid; i < HDIM; i += NTHR) sWlin[i] = Wlin[i];

    float wx[4], bb1[4], bb2[4];
#pragma unroll
    for (int g = 0; g < 4; g++) {
        int r = m + (g << 9);
        wx[g]  = Wih1[r];
        bb1[g] = bih1[r] + bhh1[r];
        bb2[g] = bih2[r] + bhh2[r];
    }
    const float blin_v = blin[0];

    // zero recurrent state (this thread's owned slots)
    g_h1a[(m << 6) + bp] = 0ULL;
    g_h1b[(m << 6) + bp] = 0ULL;
    g_h2 [(m << 6) + bp] = 0ULL;

    gridbar();   // init visible everywhere

    float c1a = 0.f, c1b = 0.f, c2a = 0.f, c2b = 0.f;
    const ull* wA  = sW1  + (cg << 11);
    const ull* wH2 = sWh2 + (cg << 11);
    const ull* wI2 = sWi2 + (cg << 11);

    const float xstrA = 0.f; (void)xstrA;

    for (int t = 0; t < TSTEPS; t++) {
        const ull* hr = (t & 1) ? g_h1b : g_h1a;   // h1 state (read)
        ull*       hw = (t & 1) ? g_h1a : g_h1b;   // h1 new   (write)

        // output dot for t-1 (h2 from previous step), partials into smem
        if (t > 0) {
            const float* h2f = (const float*)g_h2;
            sRed[tid] = h2f[(tid * 2)     * 128 + blk] * sWlin[tid * 2]
                      + h2f[(tid * 2 + 1) * 128 + blk] * sWlin[tid * 2 + 1];
        }

        // ---- phase A: gates1 = Whh1*h1_prev ; partial2 = Whh2*h2_prev ----
        ull a0 = 0, a1 = 0, a2 = 0, a3 = 0;
        ull p0 = 0, p1 = 0, p2 = 0, p3 = 0;
        const ull* hp1 = hr   + bp;
        const ull* hp2 = g_h2 + bp;
#pragma unroll 4
        for (int k = 0; k < HDIM; k += 2) {
            ull h1x = hp1[k << 6], h1y = hp1[(k + 1) << 6];
            ull h2x = hp2[k << 6], h2y = hp2[(k + 1) << 6];
            ulonglong2 w;
            w = *(const ulonglong2*)(wA  + k);        a0 = ffma2(h1x, w.x, a0); a0 = ffma2(h1y, w.y, a0);
            w = *(const ulonglong2*)(wA  + 512 + k);  a1 = ffma2(h1x, w.x, a1); a1 = ffma2(h1y, w.y, a1);
            w = *(const ulonglong2*)(wA  + 1024 + k); a2 = ffma2(h1x, w.x, a2); a2 = ffma2(h1y, w.y, a2);
            w = *(const ulonglong2*)(wA  + 1536 + k); a3 = ffma2(h1x, w.x, a3); a3 = ffma2(h1y, w.y, a3);
            w = *(const ulonglong2*)(wH2 + k);        p0 = ffma2(h2x, w.x, p0); p0 = ffma2(h2y, w.y, p0);
            w = *(const ulonglong2*)(wH2 + 512 + k);  p1 = ffma2(h2x, w.x, p1); p1 = ffma2(h2y, w.y, p1);
            w = *(const ulonglong2*)(wH2 + 1024 + k); p2 = ffma2(h2x, w.x, p2); p2 = ffma2(h2y, w.y, p2);
            w = *(const ulonglong2*)(wH2 + 1536 + k); p3 = ffma2(h2x, w.x, p3); p3 = ffma2(h2y, w.y, p3);
        }

        // ---- layer-1 elementwise update ----
        const float xa = x[(bp * 2)     * TSTEPS + t];
        const float xb = x[(bp * 2 + 1) * TSTEPS + t];
        {
            float gi = f2lo(a0) + bb1[0] + xa * wx[0];
            float gf = f2lo(a1) + bb1[1] + xa * wx[1];
            float gg = f2lo(a2) + bb1[2] + xa * wx[2];
            float go = f2lo(a3) + bb1[3] + xa * wx[3];
            c1a = sigf(gf) * c1a + sigf(gi) * tanhf(gg);
            float h1na = sigf(go) * tanhf(c1a);

            gi = f2hi(a0) + bb1[0] + xb * wx[0];
            gf = f2hi(a1) + bb1[1] + xb * wx[1];
            gg = f2hi(a2) + bb1[2] + xb * wx[2];
            go = f2hi(a3) + bb1[3] + xb * wx[3];
            c1b = sigf(gf) * c1b + sigf(gi) * tanhf(gg);
            float h1nb = sigf(go) * tanhf(c1b);

            hw[(m << 6) + bp] = packf2(h1na, h1nb);
        }

        // finish out[t-1] reduction (sRed valid, needs block sync)
        __syncthreads();
        if (t > 0 && tid < 32) {
            float s = sRed[tid]       + sRed[tid + 32]  + sRed[tid + 64]  + sRed[tid + 96]
                    + sRed[tid + 128] + sRed[tid + 160] + sRed[tid + 192] + sRed[tid + 224];
            s += __shfl_down_sync(0xffffffffu, s, 16);
            s += __shfl_down_sync(0xffffffffu, s, 8);
            s += __shfl_down_sync(0xffffffffu, s, 4);
            s += __shfl_down_sync(0xffffffffu, s, 2);
            s += __shfl_down_sync(0xffffffffu, s, 1);
            if (tid == 0) out[blk * TSTEPS + (t - 1)] = s + blin_v;
        }

        gridbar();   // h1 visible to all

        // ---- phase B: gates2 += Wih2 * h1_new ----
        const ull* hpn = hw + bp;
#pragma unroll 4
        for (int k = 0; k < HDIM; k += 2) {
            ull hx = hpn[k << 6], hy = hpn[(k + 1) << 6];
            ulonglong2 w;
            w = *(const ulonglong2*)(wI2 + k);        p0 = ffma2(hx, w.x, p0); p0 = ffma2(hy, w.y, p0);
            w = *(const ulonglong2*)(wI2 + 512 + k);  p1 = ffma2(hx, w.x, p1); p1 = ffma2(hy, w.y, p1);
            w = *(const ulonglong2*)(wI2 + 1024 + k); p2 = ffma2(hx, w.x, p2); p2 = ffma2(hy, w.y, p2);
            w = *(const ulonglong2*)(wI2 + 1536 + k); p3 = ffma2(hx, w.x, p3); p3 = ffma2(hy, w.y, p3);
        }

        // ---- layer-2 elementwise update ----
        {
            float gi = f2lo(p0) + bb2[0];
            float gf = f2lo(p1) + bb2[1];
            float gg = f2lo(p2) + bb2[2];
            float go = f2lo(p3) + bb2[3];
            c2a = sigf(gf) * c2a + sigf(gi) * tanhf(gg);
            float h2na = sigf(go) * tanhf(c2a);

            gi = f2hi(p0) + bb2[0];
            gf = f2hi(p1) + bb2[1];
            gg = f2hi(p2) + bb2[2];
            go = f2hi(p3) + bb2[3];
            c2b = sigf(gf) * c2b + sigf(gi) * tanhf(gg);
            float h2nb = sigf(go) * tanhf(c2b);

            g_h2[(m << 6) + bp] = packf2(h2na, h2nb);
        }

        gridbar();   // h2 visible to all
    }

    // final output column t = T-1
    {
        const float* h2f = (const float*)g_h2;
        sRed[tid] = h2f[(tid * 2)     * 128 + blk] * sWlin[tid * 2]
                  + h2f[(tid * 2 + 1) * 128 + blk] * sWlin[tid * 2 + 1];
        __syncthreads();
        if (tid < 32) {
            float s = sRed[tid]       + sRed[tid + 32]  + sRed[tid + 64]  + sRed[tid + 96]
                    + sRed[tid + 128] + sRed[tid + 160] + sRed[tid + 192] + sRed[tid + 224];
            s += __shfl_down_sync(0xffffffffu, s, 16);
            s += __shfl_down_sync(0xffffffffu, s, 8);
            s += __shfl_down_sync(0xffffffffu, s, 4);
            s += __shfl_down_sync(0xffffffffu, s, 2);
            s += __shfl_down_sync(0xffffffffu, s, 1);
            if (tid == 0) out[blk * TSTEPS + (TSTEPS - 1)] = s + blin_v;
        }
    }
}

extern "C" void kernel_launch(void* const* d_in, const int* in_sizes, int n_in,
                              void* d_out, int out_size) {
    const float* x    = (const float*)d_in[0];
    const float* Wih1 = (const float*)d_in[1];
    const float* Whh1 = (const float*)d_in[2];
    const float* bih1 = (const float*)d_in[3];
    const float* bhh1 = (const float*)d_in[4];
    const float* Wih2 = (const float*)d_in[5];
    const float* Whh2 = (const float*)d_in[6];
    const float* bih2 = (const float*)d_in[7];
    const float* bhh2 = (const float*)d_in[8];
    const float* Wlin = (const float*)d_in[9];
    const float* blin = (const float*)d_in[10];
    float* out = (float*)d_out;

    const size_t smem = (size_t)(3 * 16 * HDIM) * sizeof(ull)   // packed weights
                      + (size_t)HDIM * sizeof(float)            // Wlin
                      + (size_t)NTHR * sizeof(float);           // reduction
    cudaFuncSetAttribute(lstm_persistent,
                         cudaFuncAttributeMaxDynamicSharedMemorySize, (int)smem);

    lstm_persistent<<<NBLK, NTHR, smem>>>(x, Wih1, Whh1, bih1, bhh1,
                                          Wih2, Whh2, bih2, bhh2,
                                          Wlin, blin, out);
}

// round 5
// speedup vs baseline: 1.2052x; 1.2052x over previous
#include <cuda_runtime.h>

typedef unsigned long long ull;

#define NBLK 128
#define NTHR 256
#define TT   1024
#define HH   512

// -------- packed f32x2 helpers --------
__device__ __forceinline__ ull ffma2(ull a, ull b, ull c) {
    ull d;
    asm("fma.rn.f32x2 %0, %1, %2, %3;" : "=l"(d) : "l"(a), "l"(b), "l"(c));
    return d;
}
__device__ __forceinline__ float f2lo(ull v) {
    return __uint_as_float((unsigned)(v & 0xffffffffULL));
}
__device__ __forceinline__ float f2hi(ull v) {
    return __uint_as_float((unsigned)(v >> 32));
}
__device__ __forceinline__ ull packf2(float a, float b) {
    return ((ull)__float_as_uint(b) << 32) | (ull)__float_as_uint(a);
}
__device__ __forceinline__ float sigf(float v) {
    return __fdividef(1.0f, 1.0f + __expf(-v));
}

// -------- global state (16B-aligned: inner loops use 128-bit loads) --------
__device__ __align__(16) ull g_h1a[HH * 64];   // h1 ping  [k][pair]
__device__ __align__(16) ull g_h1b[HH * 64];   // h1 pong
__device__ __align__(16) ull g_h2 [HH * 64];   // h2       [k][pair]
__device__ unsigned g_cnt;
__device__ unsigned g_epoch;

// -------- grid-wide barrier (epoch/counter; proven in R2) --------
__device__ __forceinline__ void gridbar() {
    __threadfence();                 // release + L1D invalidate (gpu scope)
    __syncthreads();
    if (threadIdx.x == 0) {
        unsigned e;
        asm volatile("ld.acquire.gpu.u32 %0, [%1];" : "=r"(e) : "l"(&g_epoch));
        unsigned r = atomicAdd(&g_cnt, 1u);
        if (r == NBLK - 1) {
            atomicExch(&g_cnt, 0u);
            __threadfence();
            atomicAdd(&g_epoch, 1u);
        } else {
            unsigned cur;
            do {
                asm volatile("ld.acquire.gpu.u32 %0, [%1];" : "=r"(cur) : "l"(&g_epoch));
            } while (cur == e);
        }
    }
    __syncthreads();
}

__global__ void __launch_bounds__(NTHR, 1)
lstm_persistent(const float* __restrict__ x,
                const float* __restrict__ Wih1, const float* __restrict__ Whh1,
                const float* __restrict__ bih1, const float* __restrict__ bhh1,
                const float* __restrict__ Wih2, const float* __restrict__ Whh2,
                const float* __restrict__ bih2, const float* __restrict__ bhh2,
                const float* __restrict__ Wlin, const float* __restrict__ blin,
                float* __restrict__ out)
{
    extern __shared__ __align__(16) ull sm[];
    ull*   sW1   = sm;                     // Whh1 dup, layout [k*16 + s], s = col*4+gate
    ull*   sWh2  = sm + 8192;              // Whh2 dup
    ull*   sWi2  = sm + 16384;             // Wih2 dup
    ull*   pSm   = sm + 24576;             // layer-2 partials [s*64 + pair], 1024 ull
    float* sWlin = (float*)(sm + 25600);   // 512 floats
    float* sRed  = (float*)(sm + 25856);   // 256 floats

    const int tid  = threadIdx.x;
    const int blk  = blockIdx.x;
    const int warp = tid >> 5;
    const int lane = tid & 31;
    const int col  = lane >> 3;        // 0..3 : which hidden column of this block
    const int pg   = lane & 7;         // 0..7 : pair-group within warp strip
    const int m    = (blk << 2) + col; // owned hidden column (global)

    // ---- duplicated weights into smem, k-major 16-row layout ----
    for (int idx = tid; idx < 16 * HH; idx += NTHR) {
        int k = idx >> 4, s = idx & 15;
        int c = s >> 2, g = s & 3;
        int r = (blk << 2) + c + (g << 9);
        unsigned u;
        u = __float_as_uint(Whh1[r * HH + k]); sW1[idx]  = ((ull)u << 32) | u;
        u = __float_as_uint(Whh2[r * HH + k]); sWh2[idx] = ((ull)u << 32) | u;
        u = __float_as_uint(Wih2[r * HH + k]); sWi2[idx] = ((ull)u << 32) | u;
    }
    for (int i = tid; i < HH; i += NTHR) sWlin[i] = Wlin[i];

    float wx[4], bb1[4], bb2[4];
#pragma unroll
    for (int g = 0; g < 4; g++) {
        int r = m + (g << 9);
        wx[g]  = Wih1[r];
        bb1[g] = bih1[r] + bhh1[r];
        bb2[g] = bih2[r] + bhh2[r];
    }
    const float blin_v = blin[0];

    // zero this block's slice of the recurrent state
    g_h1a[(blk << 8) + tid] = 0ULL;
    g_h2 [(blk << 8) + tid] = 0ULL;

    gridbar();   // init visible everywhere

    const bool isA1 = (warp < 4);
    const int  w4   = warp & 3;
    const int  pbA  = w4 << 4;             // phase-A strip base pair
    const int  prA  = pbA + (pg << 1);     // first of this lane's 2 pairs
    const int  prB  = (warp << 3) + pg;    // phase-B pair
    const ull* wA   = (isA1 ? sW1 : sWh2) + (col << 2);
    const ull* wB2  = sWi2 + (col << 2);

    float c1[4] = {0.f, 0.f, 0.f, 0.f};
    float c2[2] = {0.f, 0.f};

    for (int t = 0; t < TT; t++) {
        const ull* hr = (t & 1) ? g_h1b : g_h1a;
        ull*       hw = (t & 1) ? g_h1a : g_h1b;

        // prefetch x for this lane's 4 batches (overlaps phase A)
        float xv[4];
        if (isA1) {
#pragma unroll
            for (int pp = 0; pp < 2; pp++) {
                int pr = prA + pp;
                xv[pp * 2 + 0] = x[(pr * 2 + 0) * TT + t];
                xv[pp * 2 + 1] = x[(pr * 2 + 1) * TT + t];
            }
        }

        // out[t-1] partial dot from prev-step h2 (stable since last barrier)
        if (t > 0) {
            int k0 = tid << 1;
            ull ha = g_h2[(k0 << 6) + (blk >> 1)];
            ull hb = g_h2[((k0 + 1) << 6) + (blk >> 1)];
            float va = (blk & 1) ? f2hi(ha) : f2lo(ha);
            float vb = (blk & 1) ? f2hi(hb) : f2lo(hb);
            sRed[tid] = va * sWlin[k0] + vb * sWlin[k0 + 1];
        }

        // ---- phase A: warps0-3 gates1 = Whh1*h1 ; warps4-7 part = Whh2*h2 ----
        const ull* hB = (isA1 ? hr : (const ull*)g_h2) + prA;
        ull acc[8];
#pragma unroll
        for (int i = 0; i < 8; i++) acc[i] = 0ULL;
#pragma unroll 4
        for (int k = 0; k < HH; k += 2) {
            ulonglong2 h0 = *(const ulonglong2*)(hB + (k << 6));
            ulonglong2 h1 = *(const ulonglong2*)(hB + ((k + 1) << 6));
            ulonglong2 wa = *(const ulonglong2*)(wA + (k << 4));
            ulonglong2 wb = *(const ulonglong2*)(wA + (k << 4) + 2);
            ulonglong2 wc = *(const ulonglong2*)(wA + ((k + 1) << 4));
            ulonglong2 wd = *(const ulonglong2*)(wA + ((k + 1) << 4) + 2);
            acc[0] = ffma2(wa.x, h0.x, acc[0]); acc[1] = ffma2(wa.x, h0.y, acc[1]);
            acc[2] = ffma2(wa.y, h0.x, acc[2]); acc[3] = ffma2(wa.y, h0.y, acc[3]);
            acc[4] = ffma2(wb.x, h0.x, acc[4]); acc[5] = ffma2(wb.x, h0.y, acc[5]);
            acc[6] = ffma2(wb.y, h0.x, acc[6]); acc[7] = ffma2(wb.y, h0.y, acc[7]);
            acc[0] = ffma2(wc.x, h1.x, acc[0]); acc[1] = ffma2(wc.x, h1.y, acc[1]);
            acc[2] = ffma2(wc.y, h1.x, acc[2]); acc[3] = ffma2(wc.y, h1.y, acc[3]);
            acc[4] = ffma2(wd.x, h1.x, acc[4]); acc[5] = ffma2(wd.x, h1.y, acc[5]);
            acc[6] = ffma2(wd.y, h1.x, acc[6]); acc[7] = ffma2(wd.y, h1.y, acc[7]);
        }

        if (isA1) {
            // layer-1 elementwise for 2 pairs (4 batches); write h1 to global
#pragma unroll
            for (int pp = 0; pp < 2; pp++) {
                int pr = prA + pp;
                float gi = f2lo(acc[0 + pp]) + bb1[0] + xv[pp * 2] * wx[0];
                float gf = f2lo(acc[2 + pp]) + bb1[1] + xv[pp * 2] * wx[1];
                float gg = f2lo(acc[4 + pp]) + bb1[2] + xv[pp * 2] * wx[2];
                float go = f2lo(acc[6 + pp]) + bb1[3] + xv[pp * 2] * wx[3];
                float cn = sigf(gf) * c1[pp * 2] + sigf(gi) * tanhf(gg);
                c1[pp * 2] = cn;
                float hlo = sigf(go) * tanhf(cn);

                gi = f2hi(acc[0 + pp]) + bb1[0] + xv[pp * 2 + 1] * wx[0];
                gf = f2hi(acc[2 + pp]) + bb1[1] + xv[pp * 2 + 1] * wx[1];
                gg = f2hi(acc[4 + pp]) + bb1[2] + xv[pp * 2 + 1] * wx[2];
                go = f2hi(acc[6 + pp]) + bb1[3] + xv[pp * 2 + 1] * wx[3];
                float cn2 = sigf(gf) * c1[pp * 2 + 1] + sigf(gi) * tanhf(gg);
                c1[pp * 2 + 1] = cn2;
                float hhi = sigf(go) * tanhf(cn2);

                hw[(m << 6) + pr] = packf2(hlo, hhi);
            }
        } else {
            // hand layer-2 partial gates to phase-B owners via smem
#pragma unroll
            for (int g = 0; g < 4; g++) {
                ulonglong2 v;
                v.x = acc[g * 2 + 0];
                v.y = acc[g * 2 + 1];
                *(ulonglong2*)(pSm + (((col << 2) + g) << 6) + prA) = v;
            }
        }

        gridbar();   // bar1: h1[t] global + pSm + sRed visible

        // finish out[t-1]
        if (t > 0 && tid < 32) {
            float s = sRed[tid]       + sRed[tid + 32]  + sRed[tid + 64]  + sRed[tid + 96]
                    + sRed[tid + 128] + sRed[tid + 160] + sRed[tid + 192] + sRed[tid + 224];
            s += __shfl_down_sync(0xffffffffu, s, 16);
            s += __shfl_down_sync(0xffffffffu, s, 8);
            s += __shfl_down_sync(0xffffffffu, s, 4);
            s += __shfl_down_sync(0xffffffffu, s, 2);
            s += __shfl_down_sync(0xffffffffu, s, 1);
            if (tid == 0) out[blk * TT + (t - 1)] = s + blin_v;
        }

        // ---- phase B: gates2 = pSm + Wih2 * h1_new (all 8 warps) ----
        ull a4[4];
#pragma unroll
        for (int g = 0; g < 4; g++)
            a4[g] = pSm[(((col << 2) + g) << 6) + prB];
        const ull* hN = hw + prB;
#pragma unroll 4
        for (int k = 0; k < HH; k += 2) {
            ull h0 = hN[k << 6];
            ull h1 = hN[(k + 1) << 6];
            ulonglong2 wa = *(const ulonglong2*)(wB2 + (k << 4));
            ulonglong2 wb = *(const ulonglong2*)(wB2 + (k << 4) + 2);
            ulonglong2 wc = *(const ulonglong2*)(wB2 + ((k + 1) << 4));
            ulonglong2 wd = *(const ulonglong2*)(wB2 + ((k + 1) << 4) + 2);
            a4[0] = ffma2(wa.x, h0, a4[0]); a4[1] = ffma2(wa.y, h0, a4[1]);
            a4[2] = ffma2(wb.x, h0, a4[2]); a4[3] = ffma2(wb.y, h0, a4[3]);
            a4[0] = ffma2(wc.x, h1, a4[0]); a4[1] = ffma2(wc.y, h1, a4[1]);
            a4[2] = ffma2(wd.x, h1, a4[2]); a4[3] = ffma2(wd.y, h1, a4[3]);
        }

        // ---- layer-2 elementwise (2 batches) ; write h2 to global ----
        {
            float gi = f2lo(a4[0]) + bb2[0];
            float gf = f2lo(a4[1]) + bb2[1];
            float gg = f2lo(a4[2]) + bb2[2];
            float go = f2lo(a4[3]) + bb2[3];
            float cn = sigf(gf) * c2[0] + sigf(gi) * tanhf(gg);
            c2[0] = cn;
            float hlo = sigf(go) * tanhf(cn);

            gi = f2hi(a4[0]) + bb2[0];
            gf = f2hi(a4[1]) + bb2[1];
            gg = f2hi(a4[2]) + bb2[2];
            go = f2hi(a4[3]) + bb2[3];
            float cn2 = sigf(gf) * c2[1] + sigf(gi) * tanhf(gg);
            c2[1] = cn2;
            float hhi = sigf(go) * tanhf(cn2);

            g_h2[(m << 6) + prB] = packf2(hlo, hhi);
        }

        gridbar();   // bar2: h2[t] visible
    }

    // final output column t = TT-1
    {
        int k0 = tid << 1;
        ull ha = g_h2[(k0 << 6) + (blk >> 1)];
        ull hb = g_h2[((k0 + 1) << 6) + (blk >> 1)];
        float va = (blk & 1) ? f2hi(ha) : f2lo(ha);
        float vb = (blk & 1) ? f2hi(hb) : f2lo(hb);
        sRed[tid] = va * sWlin[k0] + vb * sWlin[k0 + 1];
        __syncthreads();
        if (tid < 32) {
            float s = sRed[tid]       + sRed[tid + 32]  + sRed[tid + 64]  + sRed[tid + 96]
                    + sRed[tid + 128] + sRed[tid + 160] + sRed[tid + 192] + sRed[tid + 224];
            s += __shfl_down_sync(0xffffffffu, s, 16);
            s += __shfl_down_sync(0xffffffffu, s, 8);
            s += __shfl_down_sync(0xffffffffu, s, 4);
            s += __shfl_down_sync(0xffffffffu, s, 2);
            s += __shfl_down_sync(0xffffffffu, s, 1);
            if (tid == 0) out[blk * TT + (TT - 1)] = s + blin_v;
        }
    }
}

extern "C" void kernel_launch(void* const* d_in, const int* in_sizes, int n_in,
                              void* d_out, int out_size) {
    const float* x    = (const float*)d_in[0];
    const float* Wih1 = (const float*)d_in[1];
    const float* Whh1 = (const float*)d_in[2];
    const float* bih1 = (const float*)d_in[3];
    const float* bhh1 = (const float*)d_in[4];
    const float* Wih2 = (const float*)d_in[5];
    const float* Whh2 = (const float*)d_in[6];
    const float* bih2 = (const float*)d_in[7];
    const float* bhh2 = (const float*)d_in[8];
    const float* Wlin = (const float*)d_in[9];
    const float* blin = (const float*)d_in[10];
    float* out = (float*)d_out;

    // smem: 3*8192 ull weights + 1024 ull partials + 512f Wlin + 256f red
    const size_t smem = (size_t)25856 * sizeof(ull) + 1024;
    cudaFuncSetAttribute(lstm_persistent,
                         cudaFuncAttributeMaxDynamicSharedMemorySize, (int)smem);

    lstm_persistent<<<NBLK, NTHR, smem>>>(x, Wih1, Whh1, bih1, bhh1,
                                          Wih2, Whh2, bih2, bhh2,
                                          Wlin, blin, out);
}

// round 6
// speedup vs baseline: 1.4448x; 1.1988x over previous
#include <cuda_runtime.h>

typedef unsigned long long ull;

#define NBLK 128
#define NTHR 512
#define TT   1024
#define HH   512

// -------- packed f32x2 helpers --------
__device__ __forceinline__ ull ffma2(ull a, ull b, ull c) {
    ull d;
    asm("fma.rn.f32x2 %0, %1, %2, %3;" : "=l"(d) : "l"(a), "l"(b), "l"(c));
    return d;
}
__device__ __forceinline__ ull addf2(ull a, ull b) {
    ull d;
    asm("add.rn.f32x2 %0, %1, %2;" : "=l"(d) : "l"(a), "l"(b));
    return d;
}
__device__ __forceinline__ float f2lo(ull v) {
    return __uint_as_float((unsigned)(v & 0xffffffffULL));
}
__device__ __forceinline__ float f2hi(ull v) {
    return __uint_as_float((unsigned)(v >> 32));
}
__device__ __forceinline__ ull packf2(float a, float b) {
    return ((ull)__float_as_uint(b) << 32) | (ull)__float_as_uint(a);
}
__device__ __forceinline__ float sigf(float v) {
    return __fdividef(1.0f, 1.0f + __expf(-v));
}
// L2-scope loads for cross-SM h state (no L1 staleness, no flush needed)
__device__ __forceinline__ ulonglong2 ldcg2(const ull* p) {
    ulonglong2 v;
    asm volatile("ld.global.cg.v2.u64 {%0,%1}, [%2];" : "=l"(v.x), "=l"(v.y) : "l"(p));
    return v;
}
__device__ __forceinline__ ull ldcg1(const ull* p) {
    ull v;
    asm volatile("ld.global.cg.u64 %0, [%1];" : "=l"(v) : "l"(p));
    return v;
}

// -------- global state (16B-aligned: 128-bit loads) --------
__device__ __align__(16) ull g_h1a[HH * 64];   // h1 ping  [k][pair]
__device__ __align__(16) ull g_h1b[HH * 64];   // h1 pong
__device__ __align__(16) ull g_h2 [HH * 64];   // h2       [k][pair]
__device__ unsigned g_cnt;
__device__ unsigned g_epoch;

// -------- light grid barrier: syncthreads + single-thread release/acquire ----
__device__ __forceinline__ void gridbar() {
    __syncthreads();
    if (threadIdx.x == 0) {
        unsigned e;
        asm volatile("ld.acquire.gpu.u32 %0, [%1];" : "=r"(e) : "l"(&g_epoch));
        unsigned r;
        asm volatile("atom.add.release.gpu.u32 %0, [%1], %2;"
                     : "=r"(r) : "l"(&g_cnt), "r"(1u));
        if (r == NBLK - 1) {
            asm volatile("st.relaxed.gpu.u32 [%0], %1;" :: "l"(&g_cnt), "r"(0u));
            asm volatile("red.release.gpu.add.u32 [%0], %1;" :: "l"(&g_epoch), "r"(1u));
        } else {
            unsigned cur;
            do {
                asm volatile("ld.acquire.gpu.u32 %0, [%1];" : "=r"(cur) : "l"(&g_epoch));
            } while (cur == e);
        }
    }
    __syncthreads();
}

__global__ void __launch_bounds__(NTHR, 1)
lstm_persistent(const float* __restrict__ x,
                const float* __restrict__ Wih1, const float* __restrict__ Whh1,
                const float* __restrict__ bih1, const float* __restrict__ bhh1,
                const float* __restrict__ Wih2, const float* __restrict__ Whh2,
                const float* __restrict__ bih2, const float* __restrict__ bhh2,
                const float* __restrict__ Wlin, const float* __restrict__ blin,
                float* __restrict__ out)
{
    extern __shared__ __align__(16) ull sm[];
    ull*   sW1   = sm;                     // Whh1 dup [k*16 + s], s = col*4+gate
    ull*   sWh2  = sm + 8192;              // Whh2 dup
    ull*   sWi2  = sm + 16384;             // Wih2 dup
    ull*   pSm   = sm + 24576;             // Whh2*h2 partials [khalf][s][pair] 2048
    ull*   sG    = sm + 26624;             // k-half-1 partial exchange [s][pair] 1024
    float* sWlin = (float*)(sm + 27648);   // 512 f
    float* sRed  = (float*)(sm + 27904);   // 512 f

    const int tid   = threadIdx.x;
    const int blk   = blockIdx.x;
    const int warp  = tid >> 5;
    const int lane  = tid & 31;
    const int col   = lane >> 3;          // 0..3 hidden column of this block
    const int pg    = lane & 7;           // 0..7 pair group
    const int m     = (blk << 2) + col;   // owned hidden column (global)
    const int khalf = warp >> 3;          // 0/1 : k in [0,256) or [256,512)
    const int w8    = warp & 7;
    const bool isA1 = (w8 < 4);
    const int  w4   = w8 & 3;
    const int  prA  = (w4 << 4) + (pg << 1);  // phase-A: 2 pairs starting here
    const int  prB  = (w8 << 3) + pg;         // phase-B: 1 pair
    const int  k0   = khalf << 8;

    // ---- duplicated weights into smem, k-major 16-row layout ----
    for (int idx = tid; idx < 16 * HH; idx += NTHR) {
        int k = idx >> 4, s = idx & 15;
        int c = s >> 2, g = s & 3;
        int r = (blk << 2) + c + (g << 9);
        unsigned u;
        u = __float_as_uint(Whh1[r * HH + k]); sW1[idx]  = ((ull)u << 32) | u;
        u = __float_as_uint(Whh2[r * HH + k]); sWh2[idx] = ((ull)u << 32) | u;
        u = __float_as_uint(Wih2[r * HH + k]); sWi2[idx] = ((ull)u << 32) | u;
    }
    for (int i = tid; i < HH; i += NTHR) sWlin[i] = Wlin[i];

    float wx[4], bb1[4], bb2[4];
#pragma unroll
    for (int g = 0; g < 4; g++) {
        int r = m + (g << 9);
        wx[g]  = Wih1[r];
        bb1[g] = bih1[r] + bhh1[r];
        bb2[g] = bih2[r] + bhh2[r];
    }
    const float blin_v = blin[0];

    if (tid < 256) {
        g_h1a[(blk << 8) + tid] = 0ULL;
        g_h2 [(blk << 8) + tid] = 0ULL;
    }

    gridbar();   // init visible everywhere

    const ull* wA  = (isA1 ? sW1 : sWh2) + (col << 2);
    const ull* wB2 = sWi2 + (col << 2);

    float c1[4] = {0.f, 0.f, 0.f, 0.f};   // layer-1 cells (warps 0-3 only)
    float c2[2] = {0.f, 0.f};             // layer-2 cells (khalf0 warps only)

    for (int t = 0; t < TT; t++) {
        const ull* hr = (t & 1) ? g_h1b : g_h1a;
        ull*       hw = (t & 1) ? g_h1a : g_h1b;

        // out[t-1] partials: each thread handles k = tid
        if (t > 0) {
            ull hv = ldcg1(&g_h2[(tid << 6) + (blk >> 1)]);
            float v = (blk & 1) ? f2hi(hv) : f2lo(hv);
            sRed[tid] = v * sWlin[tid];
        }

        // x prefetch (only layer-1 k-half-0 warps add the x term)
        float xv[4];
        if (khalf == 0 && isA1) {
#pragma unroll
            for (int pp = 0; pp < 2; pp++) {
                int pr = prA + pp;
                xv[pp * 2 + 0] = x[(pr * 2 + 0) * TT + t];
                xv[pp * 2 + 1] = x[(pr * 2 + 1) * TT + t];
            }
        }

        // ---- phase A (split-k): gates1 = Whh1*h1 ; part2 = Whh2*h2 ----
        const ull* hB = (isA1 ? hr : (const ull*)g_h2) + prA;
        ull acc[8];
#pragma unroll
        for (int i = 0; i < 8; i++) acc[i] = 0ULL;
#pragma unroll 4
        for (int k = k0; k < k0 + 256; k += 2) {
            ulonglong2 h0 = ldcg2(hB + (k << 6));
            ulonglong2 h1 = ldcg2(hB + ((k + 1) << 6));
            ulonglong2 wa = *(const ulonglong2*)(wA + (k << 4));
            ulonglong2 wb = *(const ulonglong2*)(wA + (k << 4) + 2);
            ulonglong2 wc = *(const ulonglong2*)(wA + ((k + 1) << 4));
            ulonglong2 wd = *(const ulonglong2*)(wA + ((k + 1) << 4) + 2);
            acc[0] = ffma2(wa.x, h0.x, acc[0]); acc[1] = ffma2(wa.x, h0.y, acc[1]);
            acc[2] = ffma2(wa.y, h0.x, acc[2]); acc[3] = ffma2(wa.y, h0.y, acc[3]);
            acc[4] = ffma2(wb.x, h0.x, acc[4]); acc[5] = ffma2(wb.x, h0.y, acc[5]);
            acc[6] = ffma2(wb.y, h0.x, acc[6]); acc[7] = ffma2(wb.y, h0.y, acc[7]);
            acc[0] = ffma2(wc.x, h1.x, acc[0]); acc[1] = ffma2(wc.x, h1.y, acc[1]);
            acc[2] = ffma2(wc.y, h1.x, acc[2]); acc[3] = ffma2(wc.y, h1.y, acc[3]);
            acc[4] = ffma2(wd.x, h1.x, acc[4]); acc[5] = ffma2(wd.x, h1.y, acc[5]);
            acc[6] = ffma2(wd.y, h1.x, acc[6]); acc[7] = ffma2(wd.y, h1.y, acc[7]);
        }

        if (isA1) {
            if (khalf == 1) {
                // hand gates1 k-half-1 partial to warps 0-3
#pragma unroll
                for (int g = 0; g < 4; g++) {
                    ulonglong2 v; v.x = acc[g * 2]; v.y = acc[g * 2 + 1];
                    *(ulonglong2*)(sG + (((col << 2) + g) << 6) + prA) = v;
                }
            }
        } else {
            // Whh2*h2 partial for phase B (both halves kept)
#pragma unroll
            for (int g = 0; g < 4; g++) {
                ulonglong2 v; v.x = acc[g * 2]; v.y = acc[g * 2 + 1];
                *(ulonglong2*)(pSm + (khalf << 10) + (((col << 2) + g) << 6) + prA) = v;
            }
        }
        __syncthreads();

        // out[t-1] final reduce on warp 15 (off the h1 critical path)
        if (t > 0 && warp == 15) {
            float s = 0.f;
#pragma unroll
            for (int j = 0; j < 16; j++) s += sRed[lane + (j << 5)];
            s += __shfl_down_sync(0xffffffffu, s, 16);
            s += __shfl_down_sync(0xffffffffu, s, 8);
            s += __shfl_down_sync(0xffffffffu, s, 4);
            s += __shfl_down_sync(0xffffffffu, s, 2);
            s += __shfl_down_sync(0xffffffffu, s, 1);
            if (lane == 0) out[blk * TT + (t - 1)] = s + blin_v;
        }

        // layer-1 elementwise: warps 0-3 combine halves, update, publish h1
        if (khalf == 0 && isA1) {
#pragma unroll
            for (int g = 0; g < 4; g++) {
                ulonglong2 pv = *(const ulonglong2*)(sG + (((col << 2) + g) << 6) + prA);
                acc[g * 2 + 0] = addf2(acc[g * 2 + 0], pv.x);
                acc[g * 2 + 1] = addf2(acc[g * 2 + 1], pv.y);
            }
#pragma unroll
            for (int pp = 0; pp < 2; pp++) {
                int pr = prA + pp;
                float gi = f2lo(acc[0 + pp]) + bb1[0] + xv[pp * 2] * wx[0];
                float gf = f2lo(acc[2 + pp]) + bb1[1] + xv[pp * 2] * wx[1];
                float gg = f2lo(acc[4 + pp]) + bb1[2] + xv[pp * 2] * wx[2];
                float go = f2lo(acc[6 + pp]) + bb1[3] + xv[pp * 2] * wx[3];
                float cn = sigf(gf) * c1[pp * 2] + sigf(gi) * tanhf(gg);
                c1[pp * 2] = cn;
                float hlo = sigf(go) * tanhf(cn);

                gi = f2hi(acc[0 + pp]) + bb1[0] + xv[pp * 2 + 1] * wx[0];
                gf = f2hi(acc[2 + pp]) + bb1[1] + xv[pp * 2 + 1] * wx[1];
                gg = f2hi(acc[4 + pp]) + bb1[2] + xv[pp * 2 + 1] * wx[2];
                go = f2hi(acc[6 + pp]) + bb1[3] + xv[pp * 2 + 1] * wx[3];
                float cn2 = sigf(gf) * c1[pp * 2 + 1] + sigf(gi) * tanhf(gg);
                c1[pp * 2 + 1] = cn2;
                float hhi = sigf(go) * tanhf(cn2);

                hw[(m << 6) + pr] = packf2(hlo, hhi);
            }
        }

        gridbar();   // bar1: h1[t] visible everywhere

        // ---- phase B (split-k): gates2 = pSm(half) + Wih2 * h1_new ----
        ull a4[4];
#pragma unroll
        for (int g = 0; g < 4; g++)
            a4[g] = pSm[(khalf << 10) + (((col << 2) + g) << 6) + prB];
        const ull* hN = hw + prB;
#pragma unroll 4
        for (int k = k0; k < k0 + 256; k += 2) {
            ull h0 = ldcg1(hN + (k << 6));
            ull h1 = ldcg1(hN + ((k + 1) << 6));
            ulonglong2 wa = *(const ulonglong2*)(wB2 + (k << 4));
            ulonglong2 wb = *(const ulonglong2*)(wB2 + (k << 4) + 2);
            ulonglong2 wc = *(const ulonglong2*)(wB2 + ((k + 1) << 4));
            ulonglong2 wd = *(const ulonglong2*)(wB2 + ((k + 1) << 4) + 2);
            a4[0] = ffma2(wa.x, h0, a4[0]); a4[1] = ffma2(wa.y, h0, a4[1]);
            a4[2] = ffma2(wb.x, h0, a4[2]); a4[3] = ffma2(wb.y, h0, a4[3]);
            a4[0] = ffma2(wc.x, h1, a4[0]); a4[1] = ffma2(wc.y, h1, a4[1]);
            a4[2] = ffma2(wd.x, h1, a4[2]); a4[3] = ffma2(wd.y, h1, a4[3]);
        }

        if (khalf == 1) {
#pragma unroll
            for (int g = 0; g < 4; g++)
                sG[(((col << 2) + g) << 6) + prB] = a4[g];
        }
        __syncthreads();

        if (khalf == 0) {
#pragma unroll
            for (int g = 0; g < 4; g++)
                a4[g] = addf2(a4[g], sG[(((col << 2) + g) << 6) + prB]);

            float gi = f2lo(a4[0]) + bb2[0];
            float gf = f2lo(a4[1]) + bb2[1];
            float gg = f2lo(a4[2]) + bb2[2];
            float go = f2lo(a4[3]) + bb2[3];
            float cn = sigf(gf) * c2[0] + sigf(gi) * tanhf(gg);
            c2[0] = cn;
            float hlo = sigf(go) * tanhf(cn);

            gi = f2hi(a4[0]) + bb2[0];
            gf = f2hi(a4[1]) + bb2[1];
            gg = f2hi(a4[2]) + bb2[2];
            go = f2hi(a4[3]) + bb2[3];
            float cn2 = sigf(gf) * c2[1] + sigf(gi) * tanhf(gg);
            c2[1] = cn2;
            float hhi = sigf(go) * tanhf(cn2);

            g_h2[(m << 6) + prB] = packf2(hlo, hhi);
        }

        gridbar();   // bar2: h2[t] visible everywhere
    }

    // final output column t = TT-1
    {
        ull hv = ldcg1(&g_h2[(tid << 6) + (blk >> 1)]);
        float v = (blk & 1) ? f2hi(hv) : f2lo(hv);
        sRed[tid] = v * sWlin[tid];
        __syncthreads();
        if (warp == 15) {
            float s = 0.f;
#pragma unroll
            for (int j = 0; j < 16; j++) s += sRed[lane + (j << 5)];
            s += __shfl_down_sync(0xffffffffu, s, 16);
            s += __shfl_down_sync(0xffffffffu, s, 8);
            s += __shfl_down_sync(0xffffffffu, s, 4);
            s += __shfl_down_sync(0xffffffffu, s, 2);
            s += __shfl_down_sync(0xffffffffu, s, 1);
            if (lane == 0) out[blk * TT + (TT - 1)] = s + blin_v;
        }
    }
}

extern "C" void kernel_launch(void* const* d_in, const int* in_sizes, int n_in,
                              void* d_out, int out_size) {
    const float* x    = (const float*)d_in[0];
    const float* Wih1 = (const float*)d_in[1];
    const float* Whh1 = (const float*)d_in[2];
    const float* bih1 = (const float*)d_in[3];
    const float* bhh1 = (const float*)d_in[4];
    const float* Wih2 = (const float*)d_in[5];
    const float* Whh2 = (const float*)d_in[6];
    const float* bih2 = (const float*)d_in[7];
    const float* bhh2 = (const float*)d_in[8];
    const float* Wlin = (const float*)d_in[9];
    const float* blin = (const float*)d_in[10];
    float* out = (float*)d_out;

    // 28160 ull = 225,280 bytes of dynamic smem
    const size_t smem = (size_t)28160 * sizeof(ull);
    cudaFuncSetAttribute(lstm_persistent,
                         cudaFuncAttributeMaxDynamicSharedMemorySize, (int)smem);

    lstm_persistent<<<NBLK, NTHR, smem>>>(x, Wih1, Whh1, bih1, bhh1,
                                          Wih2, Whh2, bih2, bhh2,
                                          Wlin, blin, out);
}

// round 7
// speedup vs baseline: 1.4528x; 1.0055x over previous
#include <cuda_runtime.h>

typedef unsigned long long ull;

#define NBLK 128
#define NTHR 512
#define TT   1024
#define HH   512

// -------- packed f32x2 helpers --------
__device__ __forceinline__ ull ffma2(ull a, ull b, ull c) {
    ull d;
    asm("fma.rn.f32x2 %0, %1, %2, %3;" : "=l"(d) : "l"(a), "l"(b), "l"(c));
    return d;
}
__device__ __forceinline__ ull addf2(ull a, ull b) {
    ull d;
    asm("add.rn.f32x2 %0, %1, %2;" : "=l"(d) : "l"(a), "l"(b));
    return d;
}
__device__ __forceinline__ float f2lo(ull v) {
    return __uint_as_float((unsigned)(v & 0xffffffffULL));
}
__device__ __forceinline__ float f2hi(ull v) {
    return __uint_as_float((unsigned)(v >> 32));
}
__device__ __forceinline__ ull packf2(float a, float b) {
    return ((ull)__float_as_uint(b) << 32) | (ull)__float_as_uint(a);
}
__device__ __forceinline__ float sigf(float v) {
    return __fdividef(1.0f, 1.0f + __expf(-v));
}
// L2-scope loads for cross-SM h state (no L1 staleness, no flush needed)
__device__ __forceinline__ ulonglong2 ldcg2(const ull* p) {
    ulonglong2 v;
    asm volatile("ld.global.cg.v2.u64 {%0,%1}, [%2];" : "=l"(v.x), "=l"(v.y) : "l"(p));
    return v;
}
__device__ __forceinline__ ull ldcg1(const ull* p) {
    ull v;
    asm volatile("ld.global.cg.u64 %0, [%1];" : "=l"(v) : "l"(p));
    return v;
}

// -------- global state (16B-aligned: 128-bit loads) --------
__device__ __align__(16) ull g_h1a[HH * 64];   // h1 ping  [k][pair]
__device__ __align__(16) ull g_h1b[HH * 64];   // h1 pong
__device__ __align__(16) ull g_h2 [HH * 64];   // h2       [k][pair]
__device__ unsigned g_cnt;
__device__ unsigned g_epoch;

// -------- light grid barrier: syncthreads + single-thread release/acquire ----
__device__ __forceinline__ void gridbar() {
    __syncthreads();
    if (threadIdx.x == 0) {
        unsigned e;
        asm volatile("ld.acquire.gpu.u32 %0, [%1];" : "=r"(e) : "l"(&g_epoch));
        unsigned r;
        asm volatile("atom.add.release.gpu.u32 %0, [%1], %2;"
                     : "=r"(r) : "l"(&g_cnt), "r"(1u));
        if (r == NBLK - 1) {
            asm volatile("st.relaxed.gpu.u32 [%0], %1;" :: "l"(&g_cnt), "r"(0u));
            asm volatile("red.release.gpu.add.u32 [%0], %1;" :: "l"(&g_epoch), "r"(1u));
        } else {
            unsigned cur;
            do {
                asm volatile("ld.acquire.gpu.u32 %0, [%1];" : "=r"(cur) : "l"(&g_epoch));
            } while (cur == e);
        }
    }
    __syncthreads();
}

__global__ void __launch_bounds__(NTHR, 1)
lstm_persistent(const float* __restrict__ x,
                const float* __restrict__ Wih1, const float* __restrict__ Whh1,
                const float* __restrict__ bih1, const float* __restrict__ bhh1,
                const float* __restrict__ Wih2, const float* __restrict__ Whh2,
                const float* __restrict__ bih2, const float* __restrict__ bhh2,
                const float* __restrict__ Wlin, const float* __restrict__ blin,
                float* __restrict__ out)
{
    extern __shared__ __align__(16) ull sm[];
    ull*   sW1   = sm;                     // Whh1 dup [k*16 + s], s = col*4+gate
    ull*   sWh2  = sm + 8192;              // Whh2 dup
    ull*   sWi2  = sm + 16384;             // Wih2 dup
    ull*   pSm   = sm + 24576;             // Whh2*h2 partials [khalf][s][pair] 2048
    ull*   sG    = sm + 26624;             // k-half-1 partial exchange [s][pair] 1024
    float* sWlin = (float*)(sm + 27648);   // 512 f
    float* sRed  = (float*)(sm + 27904);   // 512 f

    const int tid   = threadIdx.x;
    const int blk   = blockIdx.x;
    const int warp  = tid >> 5;
    const int lane  = tid & 31;
    const int col   = lane >> 3;          // 0..3 hidden column of this block
    const int pg    = lane & 7;           // 0..7 pair group
    const int m     = (blk << 2) + col;   // owned hidden column (global)
    const int khalf = warp >> 3;          // 0/1 : k in [0,256) or [256,512)
    const int w8    = warp & 7;
    const bool isA1 = (w8 < 4);
    const int  w4   = w8 & 3;
    const int  prA  = (w4 << 4) + (pg << 1);  // phase-A: 2 pairs starting here
    const int  prB  = (w8 << 3) + pg;         // phase-B: 1 pair
    const int  k0   = khalf << 8;

    // ---- duplicated weights into smem, k-major 16-row layout ----
    for (int idx = tid; idx < 16 * HH; idx += NTHR) {
        int k = idx >> 4, s = idx & 15;
        int c = s >> 2, g = s & 3;
        int r = (blk << 2) + c + (g << 9);
        unsigned u;
        u = __float_as_uint(Whh1[r * HH + k]); sW1[idx]  = ((ull)u << 32) | u;
        u = __float_as_uint(Whh2[r * HH + k]); sWh2[idx] = ((ull)u << 32) | u;
        u = __float_as_uint(Wih2[r * HH + k]); sWi2[idx] = ((ull)u << 32) | u;
    }
    for (int i = tid; i < HH; i += NTHR) sWlin[i] = Wlin[i];

    float wx[4], bb1[4], bb2[4];
#pragma unroll
    for (int g = 0; g < 4; g++) {
        int r = m + (g << 9);
        wx[g]  = Wih1[r];
        bb1[g] = bih1[r] + bhh1[r];
        bb2[g] = bih2[r] + bhh2[r];
    }
    const float blin_v = blin[0];

    if (tid < 256) {
        g_h1a[(blk << 8) + tid] = 0ULL;
        g_h2 [(blk << 8) + tid] = 0ULL;
    }

    gridbar();   // init visible everywhere

    const ull* wA  = (isA1 ? sW1 : sWh2) + (col << 2);
    const ull* wB2 = sWi2 + (col << 2);

    float c1[4] = {0.f, 0.f, 0.f, 0.f};   // layer-1 cells (warps 0-3 only)
    float c2[2] = {0.f, 0.f};             // layer-2 cells (khalf0 warps only)

    for (int t = 0; t < TT; t++) {
        const ull* hr = (t & 1) ? g_h1b : g_h1a;
        ull*       hw = (t & 1) ? g_h1a : g_h1b;

        // out[t-1] partials: each thread handles k = tid
        if (t > 0) {
            ull hv = ldcg1(&g_h2[(tid << 6) + (blk >> 1)]);
            float v = (blk & 1) ? f2hi(hv) : f2lo(hv);
            sRed[tid] = v * sWlin[tid];
        }

        // x prefetch (only layer-1 k-half-0 warps add the x term)
        float xv[4];
        if (khalf == 0 && isA1) {
#pragma unroll
            for (int pp = 0; pp < 2; pp++) {
                int pr = prA + pp;
                xv[pp * 2 + 0] = x[(pr * 2 + 0) * TT + t];
                xv[pp * 2 + 1] = x[(pr * 2 + 1) * TT + t];
            }
        }

        // ---- phase A (split-k): gates1 = Whh1*h1 ; part2 = Whh2*h2 ----
        const ull* hB = (isA1 ? hr : (const ull*)g_h2) + prA;
        ull acc[8];
#pragma unroll
        for (int i = 0; i < 8; i++) acc[i] = 0ULL;
#pragma unroll 4
        for (int k = k0; k < k0 + 256; k += 2) {
            ulonglong2 h0 = ldcg2(hB + (k << 6));
            ulonglong2 h1 = ldcg2(hB + ((k + 1) << 6));
            ulonglong2 wa = *(const ulonglong2*)(wA + (k << 4));
            ulonglong2 wb = *(const ulonglong2*)(wA + (k << 4) + 2);
            ulonglong2 wc = *(const ulonglong2*)(wA + ((k + 1) << 4));
            ulonglong2 wd = *(const ulonglong2*)(wA + ((k + 1) << 4) + 2);
            acc[0] = ffma2(wa.x, h0.x, acc[0]); acc[1] = ffma2(wa.x, h0.y, acc[1]);
            acc[2] = ffma2(wa.y, h0.x, acc[2]); acc[3] = ffma2(wa.y, h0.y, acc[3]);
            acc[4] = ffma2(wb.x, h0.x, acc[4]); acc[5] = ffma2(wb.x, h0.y, acc[5]);
            acc[6] = ffma2(wb.y, h0.x, acc[6]); acc[7] = ffma2(wb.y, h0.y, acc[7]);
            acc[0] = ffma2(wc.x, h1.x, acc[0]); acc[1] = ffma2(wc.x, h1.y, acc[1]);
            acc[2] = ffma2(wc.y, h1.x, acc[2]); acc[3] = ffma2(wc.y, h1.y, acc[3]);
            acc[4] = ffma2(wd.x, h1.x, acc[4]); acc[5] = ffma2(wd.x, h1.y, acc[5]);
            acc[6] = ffma2(wd.y, h1.x, acc[6]); acc[7] = ffma2(wd.y, h1.y, acc[7]);
        }

        if (isA1) {
            if (khalf == 1) {
                // hand gates1 k-half-1 partial to warps 0-3
#pragma unroll
                for (int g = 0; g < 4; g++) {
                    ulonglong2 v; v.x = acc[g * 2]; v.y = acc[g * 2 + 1];
                    *(ulonglong2*)(sG + (((col << 2) + g) << 6) + prA) = v;
                }
            }
        } else {
            // Whh2*h2 partial for phase B (both halves kept)
#pragma unroll
            for (int g = 0; g < 4; g++) {
                ulonglong2 v; v.x = acc[g * 2]; v.y = acc[g * 2 + 1];
                *(ulonglong2*)(pSm + (khalf << 10) + (((col << 2) + g) << 6) + prA) = v;
            }
        }
        __syncthreads();

        // out[t-1] final reduce on warp 15 (off the h1 critical path)
        if (t > 0 && warp == 15) {
            float s = 0.f;
#pragma unroll
            for (int j = 0; j < 16; j++) s += sRed[lane + (j << 5)];
            s += __shfl_down_sync(0xffffffffu, s, 16);
            s += __shfl_down_sync(0xffffffffu, s, 8);
            s += __shfl_down_sync(0xffffffffu, s, 4);
            s += __shfl_down_sync(0xffffffffu, s, 2);
            s += __shfl_down_sync(0xffffffffu, s, 1);
            if (lane == 0) out[blk * TT + (t - 1)] = s + blin_v;
        }

        // layer-1 elementwise: warps 0-3 combine halves, update, publish h1
        if (khalf == 0 && isA1) {
#pragma unroll
            for (int g = 0; g < 4; g++) {
                ulonglong2 pv = *(const ulonglong2*)(sG + (((col << 2) + g) << 6) + prA);
                acc[g * 2 + 0] = addf2(acc[g * 2 + 0], pv.x);
                acc[g * 2 + 1] = addf2(acc[g * 2 + 1], pv.y);
            }
#pragma unroll
            for (int pp = 0; pp < 2; pp++) {
                int pr = prA + pp;
                float gi = f2lo(acc[0 + pp]) + bb1[0] + xv[pp * 2] * wx[0];
                float gf = f2lo(acc[2 + pp]) + bb1[1] + xv[pp * 2] * wx[1];
                float gg = f2lo(acc[4 + pp]) + bb1[2] + xv[pp * 2] * wx[2];
                float go = f2lo(acc[6 + pp]) + bb1[3] + xv[pp * 2] * wx[3];
                float cn = sigf(gf) * c1[pp * 2] + sigf(gi) * tanhf(gg);
                c1[pp * 2] = cn;
                float hlo = sigf(go) * tanhf(cn);

                gi = f2hi(acc[0 + pp]) + bb1[0] + xv[pp * 2 + 1] * wx[0];
                gf = f2hi(acc[2 + pp]) + bb1[1] + xv[pp * 2 + 1] * wx[1];
                gg = f2hi(acc[4 + pp]) + bb1[2] + xv[pp * 2 + 1] * wx[2];
                go = f2hi(acc[6 + pp]) + bb1[3] + xv[pp * 2 + 1] * wx[3];
                float cn2 = sigf(gf) * c1[pp * 2 + 1] + sigf(gi) * tanhf(gg);
                c1[pp * 2 + 1] = cn2;
                float hhi = sigf(go) * tanhf(cn2);

                hw[(m << 6) + pr] = packf2(hlo, hhi);
            }
        }

        gridbar();   // bar1: h1[t] visible everywhere

        // ---- phase B (split-k): gates2 = pSm(half) + Wih2 * h1_new ----
        ull a4[4];
#pragma unroll
        for (int g = 0; g < 4; g++)
            a4[g] = pSm[(khalf << 10) + (((col << 2) + g) << 6) + prB];
        const ull* hN = hw + prB;
#pragma unroll 4
        for (int k = k0; k < k0 + 256; k += 2) {
            ull h0 = ldcg1(hN + (k << 6));
            ull h1 = ldcg1(hN + ((k + 1) << 6));
            ulonglong2 wa = *(const ulonglong2*)(wB2 + (k << 4));
            ulonglong2 wb = *(const ulonglong2*)(wB2 + (k << 4) + 2);
            ulonglong2 wc = *(const ulonglong2*)(wB2 + ((k + 1) << 4));
            ulonglong2 wd = *(const ulonglong2*)(wB2 + ((k + 1) << 4) + 2);
            a4[0] = ffma2(wa.x, h0, a4[0]); a4[1] = ffma2(wa.y, h0, a4[1]);
            a4[2] = ffma2(wb.x, h0, a4[2]); a4[3] = ffma2(wb.y, h0, a4[3]);
            a4[0] = ffma2(wc.x, h1, a4[0]); a4[1] = ffma2(wc.y, h1, a4[1]);
            a4[2] = ffma2(wd.x, h1, a4[2]); a4[3] = ffma2(wd.y, h1, a4[3]);
        }

        if (khalf == 1) {
#pragma unroll
            for (int g = 0; g < 4; g++)
                sG[(((col << 2) + g) << 6) + prB] = a4[g];
        }
        __syncthreads();

        if (khalf == 0) {
#pragma unroll
            for (int g = 0; g < 4; g++)
                a4[g] = addf2(a4[g], sG[(((col << 2) + g) << 6) + prB]);

            float gi = f2lo(a4[0]) + bb2[0];
            float gf = f2lo(a4[1]) + bb2[1];
            float gg = f2lo(a4[2]) + bb2[2];
            float go = f2lo(a4[3]) + bb2[3];
            float cn = sigf(gf) * c2[0] + sigf(gi) * tanhf(gg);
            c2[0] = cn;
            float hlo = sigf(go) * tanhf(cn);

            gi = f2hi(a4[0]) + bb2[0];
            gf = f2hi(a4[1]) + bb2[1];
            gg = f2hi(a4[2]) + bb2[2];
            go = f2hi(a4[3]) + bb2[3];
            float cn2 = sigf(gf) * c2[1] + sigf(gi) * tanhf(gg);
            c2[1] = cn2;
            float hhi = sigf(go) * tanhf(cn2);

            g_h2[(m << 6) + prB] = packf2(hlo, hhi);
        }

        gridbar();   // bar2: h2[t] visible everywhere
    }

    // final output column t = TT-1
    {
        ull hv = ldcg1(&g_h2[(tid << 6) + (blk >> 1)]);
        float v = (blk & 1) ? f2hi(hv) : f2lo(hv);
        sRed[tid] = v * sWlin[tid];
        __syncthreads();
        if (warp == 15) {
            float s = 0.f;
#pragma unroll
            for (int j = 0; j < 16; j++) s += sRed[lane + (j << 5)];
            s += __shfl_down_sync(0xffffffffu, s, 16);
            s += __shfl_down_sync(0xffffffffu, s, 8);
            s += __shfl_down_sync(0xffffffffu, s, 4);
            s += __shfl_down_sync(0xffffffffu, s, 2);
            s += __shfl_down_sync(0xffffffffu, s, 1);
            if (lane == 0) out[blk * TT + (TT - 1)] = s + blin_v;
        }
    }
}

extern "C" void kernel_launch(void* const* d_in, const int* in_sizes, int n_in,
                              void* d_out, int out_size) {
    const float* x    = (const float*)d_in[0];
    const float* Wih1 = (const float*)d_in[1];
    const float* Whh1 = (const float*)d_in[2];
    const float* bih1 = (const float*)d_in[3];
    const float* bhh1 = (const float*)d_in[4];
    const float* Wih2 = (const float*)d_in[5];
    const float* Whh2 = (const float*)d_in[6];
    const float* bih2 = (const float*)d_in[7];
    const float* bhh2 = (const float*)d_in[8];
    const float* Wlin = (const float*)d_in[9];
    const float* blin = (const float*)d_in[10];
    float* out = (float*)d_out;

    // 28160 ull = 225,280 bytes of dynamic smem
    const size_t smem = (size_t)28160 * sizeof(ull);
    cudaFuncSetAttribute(lstm_persistent,
                         cudaFuncAttributeMaxDynamicSharedMemorySize, (int)smem);

    lstm_persistent<<<NBLK, NTHR, smem>>>(x, Wih1, Whh1, bih1, bhh1,
                                          Wih2, Whh2, bih2, bhh2,
                                          Wlin, blin, out);
}